// round 9
// baseline (speedup 1.0000x reference)
#include <cuda_runtime.h>
#include <cuda_fp16.h>
#include <cstdint>

constexpr int Bsz = 64, Qn = 512, Sn = 1024, Dn = 1024;

// fp16 copies: query transposed to [B,Q,D], key as [B,S,D]
__device__ __half g_qh[(size_t)Bsz * Qn * Dn];
__device__ __half g_kh[(size_t)Bsz * Sn * Dn];

// flags: g_flags[b*4+qblk] (8 producers each), g_cflag[b] (16 convert slices)
__device__ int g_flags[256];
__device__ int g_cflag[64];

// ---------------------------------------------------------------------------
// helpers (sm_80-era PTX only — harness ptxas targets plain sm_103)
// ---------------------------------------------------------------------------
__device__ __forceinline__ uint32_t smem_u32(const void* p) {
    uint32_t a;
    asm("{ .reg .u64 t; cvta.to.shared.u64 t, %1; cvt.u32.u64 %0, t; }" : "=r"(a) : "l"(p));
    return a;
}

#define CP16(dst, src) \
    asm volatile("cp.async.cg.shared.global [%0], [%1], 16;" :: "r"(dst), "l"(src) : "memory")
#define CP_COMMIT() asm volatile("cp.async.commit_group;" ::: "memory")
#define CP_WAIT(n)  asm volatile("cp.async.wait_group %0;" :: "n"(n) : "memory")

#define LDSM4(r0, r1, r2, r3, addr)                                        \
    asm volatile("ldmatrix.sync.aligned.m8n8.x4.shared.b16 {%0,%1,%2,%3}, [%4];" \
        : "=r"(r0), "=r"(r1), "=r"(r2), "=r"(r3) : "r"(addr))

#define MMA16816(d, a, b0, b1)                                             \
    asm volatile("mma.sync.aligned.m16n8k16.row.col.f32.f16.f16.f32 "      \
        "{%0,%1,%2,%3}, {%4,%5,%6,%7}, {%8,%9}, {%0,%1,%2,%3};"            \
        : "+f"((d)[0]), "+f"((d)[1]), "+f"((d)[2]), "+f"((d)[3])           \
        : "r"((a)[0]), "r"((a)[1]), "r"((a)[2]), "r"((a)[3]),              \
          "r"(b0), "r"(b1))

__device__ __forceinline__ void spin_ge(const int* fp, int target) {
    int v;
    for (;;) {
        asm volatile("ld.acquire.gpu.global.b32 %0, [%1];" : "=r"(v) : "l"(fp));
        if (v >= target) break;
        __nanosleep(64);
    }
}

struct alignas(8) Half4 { __half2 a, b; };

// ---------------------------------------------------------------------------
// Role sizing
// ---------------------------------------------------------------------------
constexpr int BM = 128, BN = 128, BKh = 64;
constexpr int NCH = Dn / BKh;             // 16
constexpr int A_BYTES  = BM * 128;        // 16 KB
constexpr int STAGE_B  = 2 * A_BYTES;     // 32 KB
constexpr int STAGES   = 3;
constexpr int DYN_SMEM = STAGES * STAGE_B + 1024;
constexpr int N_SCAN   = Bsz;             // 64
constexpr int N_CONV   = Bsz * 16;        // 1024 (8 key + 8 query slices per b)
constexpr int N_GEMM   = 4 * Bsz * 8;     // 2048
constexpr int QBLK     = 128;

// ---------------------------------------------------------------------------
// Convert role: fp32 -> fp16, per-b slices, publish g_cflag[b]
// ---------------------------------------------------------------------------
__device__ __forceinline__ void conv_body(const float* __restrict__ key,
                                          const float* __restrict__ query, int cid)
{
    const int b = cid >> 4;
    const int j = cid & 15;
    const int tid = threadIdx.x;

    if (j < 8) {
        // key slice j: S*D/8 = 131072 floats = 32768 float4
        const float4* src =
            reinterpret_cast<const float4*>(key + (size_t)b * Sn * Dn) + j * 32768;
        Half4* dst = reinterpret_cast<Half4*>(g_kh + (size_t)b * Sn * Dn) + j * 32768;
#pragma unroll 4
        for (int i = tid; i < 32768; i += 256) {
            float4 v = src[i];
            Half4 h;
            h.a = __floats2half2_rn(v.x, v.y);
            h.b = __floats2half2_rn(v.z, v.w);
            dst[i] = h;
        }
    } else {
        // query slice: 64 q rows, transpose [Q,B,D] -> [B,Q,D]
        const int qbase = (j - 8) * 64;
        for (int r = 0; r < 64; r++) {
            const int q = qbase + r;
            float4 v = reinterpret_cast<const float4*>(
                query + ((size_t)q * Bsz + b) * Dn)[tid];
            Half4 h;
            h.a = __floats2half2_rn(v.x, v.y);
            h.b = __floats2half2_rn(v.z, v.w);
            reinterpret_cast<Half4*>(g_qh + ((size_t)b * Qn + q) * Dn)[tid] = h;
        }
    }
    __threadfence();
    __syncthreads();
    if (tid == 0) atomicAdd(&g_cflag[b], 1);
}

// ---------------------------------------------------------------------------
// GEMM role (q-block outermost; gated on converts; publishes g_flags)
// ---------------------------------------------------------------------------
__device__ __forceinline__ void prefetch(uint32_t stBase,
                                         const __half* __restrict__ Ag,
                                         const __half* __restrict__ Bg,
                                         int kt, int tid)
{
    const uint32_t stA = stBase, stB = stBase + A_BYTES;
#pragma unroll
    for (int i = 0; i < 4; i++) {
        int idx = tid * 4 + i;
        int row = idx >> 3, c = idx & 7;
        uint32_t so = (uint32_t)(row * 128 + ((c * 16) ^ ((row & 7) * 16)));
        size_t go = (size_t)row * Dn + kt + c * 8;
        CP16(stA + so, Ag + go);
        CP16(stB + so, Bg + go);
    }
    CP_COMMIT();
}

__device__ __forceinline__ void gemm_body(float* __restrict__ out, char* dsm)
{
    const uint32_t raw = smem_u32(dsm);
    const uint32_t sb  = (raw + 1023) & ~1023u;
    char* alig = dsm + (sb - raw);

    const int tid  = threadIdx.x;
    const int wid  = tid >> 5, lane = tid & 31;

    const int g    = blockIdx.x - (N_SCAN + N_CONV);
    const int qblk = g >> 9;              // 0..3, outermost -> early q first
    const int rem  = g & 511;
    const int b    = rem >> 3;
    const int s0   = (rem & 7) * BN;
    const int q0   = qblk * BM;

    // gate on this b's converts (16 slices)
    if (tid == 0) spin_ge(&g_cflag[b], 16);
    __syncthreads();

    const int m0w = (wid & 1) * 64;
    const int n0w = (wid >> 1) * 32;

    const __half* Ag = g_qh + ((size_t)b * Qn + q0) * Dn;
    const __half* Bg = g_kh + ((size_t)b * Sn + s0) * Dn;

    float acc[4][4][4];
#pragma unroll
    for (int i = 0; i < 4; i++)
#pragma unroll
        for (int j = 0; j < 4; j++)
#pragma unroll
            for (int k = 0; k < 4; k++) acc[i][j][k] = 0.0f;

    const int r8    = lane & 7;
    const int rowA  = m0w + r8 + 8 * ((lane >> 3) & 1);
    const int khA   = 16 * (lane >> 4);
    const int rowB  = n0w + r8 + 8 * (lane >> 4);
    const int khB   = 16 * ((lane >> 3) & 1);
    const int swz   = r8 * 16;

    prefetch(sb + 0 * STAGE_B, Ag, Bg, 0, tid);
    prefetch(sb + 1 * STAGE_B, Ag, Bg, BKh, tid);

    for (int c = 0; c < NCH; c++) {
        if (c < NCH - 1) { CP_WAIT(1); } else { CP_WAIT(0); }
        __syncthreads();

        if (c + 2 < NCH)
            prefetch(sb + ((c + 2) % STAGES) * STAGE_B, Ag, Bg, (c + 2) * BKh, tid);

        const uint32_t stA = sb + (c % STAGES) * STAGE_B;
        const uint32_t stB = stA + A_BYTES;

#pragma unroll
        for (int ks = 0; ks < 4; ks++) {
            uint32_t a[4][4], bf[2][4];
            const int kbA = (32 * ks + khA) ^ swz;
            const int kbB = (32 * ks + khB) ^ swz;
#pragma unroll
            for (int mi = 0; mi < 4; mi++)
                LDSM4(a[mi][0], a[mi][1], a[mi][2], a[mi][3],
                      stA + (uint32_t)((rowA + mi * 16) * 128 + kbA));
#pragma unroll
            for (int gg = 0; gg < 2; gg++)
                LDSM4(bf[gg][0], bf[gg][1], bf[gg][2], bf[gg][3],
                      stB + (uint32_t)((rowB + gg * 16) * 128 + kbB));
#pragma unroll
            for (int mi = 0; mi < 4; mi++)
#pragma unroll
                for (int nt = 0; nt < 4; nt++) {
                    const int gg = nt >> 1, s2 = (nt & 1) * 2;
                    MMA16816(acc[mi][nt], a[mi], bf[gg][s2], bf[gg][s2 + 1]);
                }
        }
    }
    __syncthreads();

    // Epilogue: regs -> smem -> coalesced gmem, scale 1/32
    float* ep = reinterpret_cast<float*>(alig);
    const float scale = 0.03125f;
    const int er = lane >> 2, ec = 2 * (lane & 3);
#pragma unroll
    for (int mi = 0; mi < 4; mi++) {
        const int row0 = m0w + mi * 16 + er;
#pragma unroll
        for (int nt = 0; nt < 4; nt++) {
            const int col = n0w + nt * 8 + ec;
            float2 lo = make_float2(acc[mi][nt][0] * scale, acc[mi][nt][1] * scale);
            float2 hi = make_float2(acc[mi][nt][2] * scale, acc[mi][nt][3] * scale);
            *reinterpret_cast<float2*>(&ep[row0 * 132 + col]) = lo;
            *reinterpret_cast<float2*>(&ep[(row0 + 8) * 132 + col]) = hi;
        }
    }
    __syncthreads();

    float* obase = out + ((size_t)b * Qn + q0) * Sn + s0;
#pragma unroll 4
    for (int i = tid; i < BM * (BN / 4); i += 256) {
        int row = i >> 5, c4 = (i & 31) * 4;
        *reinterpret_cast<float4*>(obase + (size_t)row * Sn + c4) =
            *reinterpret_cast<const float4*>(&ep[row * 132 + c4]);
    }

    __threadfence();
    __syncthreads();
    if (tid == 0) atomicAdd(&g_flags[b * 4 + qblk], 1);
}

// ---------------------------------------------------------------------------
// Scan role: sequential softmax scan, depth-2 LDG prefetch within gated block
// ---------------------------------------------------------------------------
__device__ __forceinline__ void scan_body(float* __restrict__ att,
                                          const unsigned char* __restrict__ mask,
                                          float* __restrict__ state)
{
    const int b   = blockIdx.x;
    const int tid = threadIdx.x;
    const int idx = tid * 4;
    const int lane = tid & 31, w = tid >> 5;
    __shared__ __align__(16) float red[2][8];

    uchar4 mk = *reinterpret_cast<const uchar4*>(mask + (size_t)b * Sn + idx);
    float4 acc = make_float4(0.f, 0.f, 0.f, 0.f);
    float* base = att + (size_t)b * Qn * Sn;

    for (int qb = 0; qb < 4; qb++) {
        if (tid == 0) spin_ge(&g_flags[b * 4 + qb], 8);
        __syncthreads();

        const int q0 = qb * QBLK;
        float4 sc = *reinterpret_cast<const float4*>(base + (size_t)q0 * Sn + idx);
        float4 nx = *reinterpret_cast<const float4*>(base + (size_t)(q0 + 1) * Sn + idx);

        for (int qi = 0; qi < QBLK; qi++) {
            const int q = q0 + qi;
            float4 pre = make_float4(0.f, 0.f, 0.f, 0.f);
            if (qi + 2 < QBLK)
                pre = *reinterpret_cast<const float4*>(base + (size_t)(q + 2) * Sn + idx);

            float e0 = mk.x ? 0.0f : __expf(sc.x - acc.x);
            float e1 = mk.y ? 0.0f : __expf(sc.y - acc.y);
            float e2 = mk.z ? 0.0f : __expf(sc.z - acc.z);
            float e3 = mk.w ? 0.0f : __expf(sc.w - acc.w);

            float v = (e0 + e1) + (e2 + e3);
            v += __shfl_xor_sync(0xffffffffu, v, 16);
            v += __shfl_xor_sync(0xffffffffu, v, 8);
            v += __shfl_xor_sync(0xffffffffu, v, 4);
            v += __shfl_xor_sync(0xffffffffu, v, 2);
            v += __shfl_xor_sync(0xffffffffu, v, 1);
            if (lane == 0) red[q & 1][w] = v;
            __syncthreads();
            float4 r0 = *reinterpret_cast<const float4*>(&red[q & 1][0]);
            float4 r1 = *reinterpret_cast<const float4*>(&red[q & 1][4]);
            float total = ((r0.x + r0.y) + (r0.z + r0.w)) +
                          ((r1.x + r1.y) + (r1.z + r1.w));

            float inv;
            asm("rcp.approx.f32 %0, %1;" : "=f"(inv) : "f"(total));
            float4 at;
            at.x = e0 * inv; at.y = e1 * inv; at.z = e2 * inv; at.w = e3 * inv;
            *reinterpret_cast<float4*>(base + (size_t)q * Sn + idx) = at;
            acc.x += at.x; acc.y += at.y; acc.z += at.z; acc.w += at.w;
            sc = nx; nx = pre;
        }
    }
    *reinterpret_cast<float4*>(state + (size_t)b * Sn + idx) = acc;
}

// ---------------------------------------------------------------------------
// Fused kernel + flag reset
// ---------------------------------------------------------------------------
__global__ void zero_flags_kernel() {
    const int t = threadIdx.x;
    if (t < 256) g_flags[t] = 0;
    if (t < 64)  g_cflag[t] = 0;
}

__global__ __launch_bounds__(256, 2) void fused_kernel(
    float* __restrict__ att, const unsigned char* __restrict__ mask,
    float* __restrict__ state,
    const float* __restrict__ key, const float* __restrict__ query)
{
    extern __shared__ char dsm[];
    if (blockIdx.x < N_SCAN) {
        scan_body(att, mask, state);
    } else if (blockIdx.x < N_SCAN + N_CONV) {
        conv_body(key, query, blockIdx.x - N_SCAN);
    } else {
        gemm_body(att, dsm);
    }
}

// ---------------------------------------------------------------------------
// Launch
// ---------------------------------------------------------------------------
extern "C" void kernel_launch(void* const* d_in, const int* in_sizes, int n_in,
                              void* d_out, int out_size)
{
    const float*         key   = (const float*)d_in[0];          // [B, S, D]
    const float*         query = (const float*)d_in[1];          // [Q, B, D]
    const unsigned char* mask  = (const unsigned char*)d_in[2];  // [B, S]

    float* att   = (float*)d_out;                      // [B, Q, S]
    float* state = att + (size_t)Bsz * Qn * Sn;        // [B, S]

    cudaFuncSetAttribute(fused_kernel,
                         cudaFuncAttributeMaxDynamicSharedMemorySize, DYN_SMEM);

    zero_flags_kernel<<<1, 256>>>();
    fused_kernel<<<N_SCAN + N_CONV + N_GEMM, 256, DYN_SMEM>>>(
        att, mask, state, key, query);
}